// round 15
// baseline (speedup 1.0000x reference)
#include <cuda_runtime.h>
#include <math.h>

// rbfLayer, round 15: R14 shell + (a) domain-specialized 20-instr hat decode
// (sr>=0, sr<2.14, sa in [0,4] -> drop redundant abs, share subexpressions),
// (b) warp-local phase1->phase2 handoff via __syncwarp (phases already
// warp-local), block barrier deferred to just before the epilogue (first sk2
// read), so the mainloop runs barrier-free per warp.

#define PTS_PER_BLOCK 64
#define BLOCK_THREADS 256
#define SSW_STRIDE 18          // float2 per point row (16 + 2 pad)

typedef unsigned long long u64;

__device__ __forceinline__ u64 pack2(float lo, float hi) {
    u64 r;
    asm("mov.b64 %0, {%1,%2};" : "=l"(r)
        : "r"(__float_as_int(lo)), "r"(__float_as_int(hi)));
    return r;
}
__device__ __forceinline__ void unpack2(u64 v, float& lo, float& hi) {
    int a, b;
    asm("mov.b64 {%0,%1}, %2;" : "=r"(a), "=r"(b) : "l"(v));
    lo = __int_as_float(a); hi = __int_as_float(b);
}
__device__ __forceinline__ u64 fma2(u64 a, u64 b, u64 c) {
    u64 d;
    asm("fma.rn.f32x2 %0, %1, %2, %3;" : "=l"(d) : "l"(a), "l"(b), "l"(c));
    return d;
}
__device__ __forceinline__ u64 mul2(u64 a, u64 b) {
    u64 d;
    asm("mul.rn.f32x2 %0, %1, %2;" : "=l"(d) : "l"(a), "l"(b));
    return d;
}
__device__ __forceinline__ u64 add2(u64 a, u64 b) {
    u64 d;
    asm("add.rn.f32x2 %0, %1, %2;" : "=l"(d) : "l"(a), "l"(b));
    return d;
}

__device__ __forceinline__ void edge_geom(float dx, float dy,
                                          float& sr, float& sa) {
    float d2 = fmaxf(fmaf(dx, dx, dy * dy), 1e-24f);
    float rinv = rsqrtf(d2);
    sr = d2 * rinv * 1.5f;

    float ax = fabsf(dx), ay = fabsf(dy);
    float mn = fminf(ax, ay);
    float mx = fmaxf(fmaxf(ax, ay), 1e-30f);
    float tq = __fdividef(mn, mx);
    float t2 = tq * tq;
    float pl = -0.0117212f;
    pl = fmaf(pl, t2, 0.05265332f);
    pl = fmaf(pl, t2, -0.11643287f);
    pl = fmaf(pl, t2, 0.19354346f);
    pl = fmaf(pl, t2, -0.33262347f);
    pl = fmaf(pl, t2, 0.99997726f);
    float ang = pl * tq;
    if (ay > ax) ang = 1.5707963267948966f - ang;
    if (dx < 0.0f) ang = 3.141592653589793f - ang;
    float th = ang * 0.3183098861837907f;
    th = (dy < 0.0f) ? -th : th;
    sa = fmaf(th, 2.0f, 2.0f);
}

// Domain-specialized branch-free hat decode (~20 lat-4 fma-pipe instr):
//   sr in [0, 2.14): wr0 = max(0,1-sr); wr3 = max(0, sr-2)  (exact on domain)
//   sa in [0, 4]   : wa0 = max(0, max(1-sa, sa-3))          (cyclic wrap)
__device__ __forceinline__ void decode_w(float sr, float sa,
                                         float4& WA, float4& WR) {
    float s1 = sa - 1.0f;
    float s2 = sa - 2.0f;
    float s3 = sa - 3.0f;
    WA.x = fmaxf(0.0f, fmaxf(1.0f - sa, s3));
    WA.y = fmaxf(0.0f, 1.0f - fabsf(s1));
    WA.z = fmaxf(0.0f, 1.0f - fabsf(s2));
    WA.w = fmaxf(0.0f, 1.0f - fabsf(s3));

    float r1 = sr - 1.0f;
    float r2 = sr - 2.0f;
    WR.x = fmaxf(0.0f, 1.0f - sr);
    WR.y = fmaxf(0.0f, 1.0f - fabsf(r1));
    WR.z = fmaxf(0.0f, 1.0f - fabsf(r2));
    WR.w = fmaxf(0.0f, r2);
}

__device__ __forceinline__ void accum16(const float4& WA, const float4& WR,
                                        u64 fv2, u64 Zp[16]) {
    u64 t0 = mul2(pack2(WA.x, WA.x), fv2);
    u64 t1 = mul2(pack2(WA.y, WA.y), fv2);
    u64 t2 = mul2(pack2(WA.z, WA.z), fv2);
    u64 t3 = mul2(pack2(WA.w, WA.w), fv2);
    u64 r0 = pack2(WR.x, WR.x);
    u64 r1 = pack2(WR.y, WR.y);
    u64 r2 = pack2(WR.z, WR.z);
    u64 r3 = pack2(WR.w, WR.w);

    Zp[0]  = fma2(r0, t0, Zp[0]);   Zp[1]  = fma2(r0, t1, Zp[1]);
    Zp[2]  = fma2(r0, t2, Zp[2]);   Zp[3]  = fma2(r0, t3, Zp[3]);
    Zp[4]  = fma2(r1, t0, Zp[4]);   Zp[5]  = fma2(r1, t1, Zp[5]);
    Zp[6]  = fma2(r1, t2, Zp[6]);   Zp[7]  = fma2(r1, t3, Zp[7]);
    Zp[8]  = fma2(r2, t0, Zp[8]);   Zp[9]  = fma2(r2, t1, Zp[9]);
    Zp[10] = fma2(r2, t2, Zp[10]);  Zp[11] = fma2(r2, t3, Zp[11]);
    Zp[12] = fma2(r3, t0, Zp[12]);  Zp[13] = fma2(r3, t1, Zp[13]);
    Zp[14] = fma2(r3, t2, Zp[14]);  Zp[15] = fma2(r3, t3, Zp[15]);
}

__global__ __launch_bounds__(BLOCK_THREADS, 4)
void rbf_layer_kernel(const float2* __restrict__ pos,
                      const float*  __restrict__ feat,
                      const float*  __restrict__ kern,
                      const int*    __restrict__ nbrs,
                      const int*    __restrict__ rsp,
                      float*        __restrict__ out,
                      int n_pts, int n_edges)
{
    __shared__ ulonglong2 sk2[8 * 8 * 4];               // 4 KB epilogue K
    __shared__ float2 ssw[PTS_PER_BLOCK * SSW_STRIDE];  // 9.2 KB (sr,sa)

    int tid = threadIdx.x;

    // sk2 fill: one entry per thread; first READ is in the epilogue, so the
    // block barrier is deferred until just before it.
    {
        int idx = tid;
        int tt  = idx & 3;
        int nm2 = (idx >> 2) & 7;
        int i   = idx >> 5;
        int n0 = 2 * nm2, n1 = 2 * nm2 + 1;
        ulonglong2 v;
        v.x = pack2(kern[(i * 8 + 2 * tt)     * 16 + n0],
                    kern[(i * 8 + 2 * tt + 1) * 16 + n0]);
        v.y = pack2(kern[(i * 8 + 2 * tt)     * 16 + n1],
                    kern[(i * 8 + 2 * tt + 1) * 16 + n1]);
        sk2[idx] = v;
    }

    int p0 = blockIdx.x * PTS_PER_BLOCK;

    // ---- Phase 1 (warp-local): geometry -> smem for this warp's 8 points ----
    {
        int ptl = tid >> 2;                 // local point 0..63 (warp-local range)
        int g   = tid & 3;                  // edge quad 0..3
        int e0  = (p0 + ptl) * 16 + g * 4;
        int4 nbq;
        if (e0 + 3 < n_edges) {
            nbq = __ldg((const int4*)(nbrs + e0));
        } else {
            nbq.x = (e0 + 0 < n_edges) ? __ldg(nbrs + e0 + 0) : 0;
            nbq.y = (e0 + 1 < n_edges) ? __ldg(nbrs + e0 + 1) : 0;
            nbq.z = (e0 + 2 < n_edges) ? __ldg(nbrs + e0 + 2) : 0;
            nbq.w = (e0 + 3 < n_edges) ? __ldg(nbrs + e0 + 3) : 0;
        }

        int pidx = p0 + ptl;
        float2 pp = __ldg(&pos[(pidx < n_pts) ? pidx : 0]);
        float2 q0 = __ldg(&pos[nbq.x]);
        float2 q1 = __ldg(&pos[nbq.y]);
        float2 q2 = __ldg(&pos[nbq.z]);
        float2 q3 = __ldg(&pos[nbq.w]);

        float4* dst = (float4*)&ssw[ptl * SSW_STRIDE + g * 4];
        float sr0, sa0, sr1, sa1;
        edge_geom(q0.x - pp.x, q0.y - pp.y, sr0, sa0);
        edge_geom(q1.x - pp.x, q1.y - pp.y, sr1, sa1);
        dst[0] = make_float4(sr0, sa0, sr1, sa1);       // STS.128
        edge_geom(q2.x - pp.x, q2.y - pp.y, sr0, sa0);
        edge_geom(q3.x - pp.x, q3.y - pp.y, sr1, sa1);
        dst[1] = make_float4(sr0, sa0, sr1, sa1);       // STS.128
    }
    __syncwarp();   // phase1 and phase2 touch only this warp's 8-point slice

    // ---- Phase 2 (warp-local, barrier-free) ----
    int point = p0 + (tid >> 2);
    int t     = tid & 3;

    bool valid = (point < n_pts);
    int pclamp = valid ? point : 0;

    int beg = valid ? __ldg(rsp + pclamp)     : 0;
    int end = valid ? __ldg(rsp + pclamp + 1) : 0;
    int cnt = end - beg;

    bool fast = valid && (cnt == 16) && (beg == (point << 4));

    const float2* f2 = (const float2*)feat;

    u64 Zp[16];
    #pragma unroll
    for (int k = 0; k < 16; ++k) Zp[k] = 0ull;

    if (fast) {
        int lpt = point - p0;
        const float2* swp = &ssw[lpt * SSW_STRIDE];
        const int4* nb4 = (const int4*)(nbrs + beg);

        #pragma unroll
        for (int g = 0; g < 4; ++g) {
            int4 nbq = __ldg(nb4 + g);      // broadcast, L1-hot from phase 1
            float2 Fa = __ldg(&f2[(unsigned)nbq.x * 4 + t]);
            float2 Fb = __ldg(&f2[(unsigned)nbq.y * 4 + t]);
            float2 Fc = __ldg(&f2[(unsigned)nbq.z * 4 + t]);
            float2 Fd = __ldg(&f2[(unsigned)nbq.w * 4 + t]);

            float4 WA, WR;
            {
                float4 s01 = *(const float4*)(swp + g * 4);
                decode_w(s01.x, s01.y, WA, WR); accum16(WA, WR, pack2(Fa.x, Fa.y), Zp);
                decode_w(s01.z, s01.w, WA, WR); accum16(WA, WR, pack2(Fb.x, Fb.y), Zp);
            }
            {
                float4 s23 = *(const float4*)(swp + g * 4 + 2);
                decode_w(s23.x, s23.y, WA, WR); accum16(WA, WR, pack2(Fc.x, Fc.y), Zp);
                decode_w(s23.z, s23.w, WA, WR); accum16(WA, WR, pack2(Fd.x, Fd.y), Zp);
            }
        }
    } else if (valid) {
        const float2 pp = __ldg(&pos[pclamp]);
        for (int e = beg; e < end; ++e) {
            int nb = __ldg(nbrs + e);
            float2 q = __ldg(&pos[nb]);
            float sr, sa;
            edge_geom(q.x - pp.x, q.y - pp.y, sr, sa);
            float4 WA, WR;
            decode_w(sr, sa, WA, WR);
            float2 fv = __ldg(&f2[nb * 4 + t]);
            accum16(WA, WR, pack2(fv.x, fv.y), Zp);
        }
    }

    // sk2 first read below: block barrier here, where warp slack is absorbed.
    __syncthreads();

    // ---- Epilogue: smem K, two dependency chains per output ----
    float pr[8];
    #pragma unroll
    for (int i = 0; i < 8; ++i) {
        u64 a0 = 0ull, a1 = 0ull;
        #pragma unroll
        for (int nm2 = 0; nm2 < 8; nm2 += 2) {
            ulonglong2 k0 = sk2[(i * 8 + nm2)     * 4 + t];
            ulonglong2 k1 = sk2[(i * 8 + nm2 + 1) * 4 + t];
            a0 = fma2(k0.x, Zp[2 * nm2],     a0);
            a0 = fma2(k0.y, Zp[2 * nm2 + 1], a0);
            a1 = fma2(k1.x, Zp[2 * nm2 + 2], a1);
            a1 = fma2(k1.y, Zp[2 * nm2 + 3], a1);
        }
        u64 acc = add2(a0, a1);
        float lo, hi;
        unpack2(acc, lo, hi);
        pr[i] = lo + hi;
    }

    #pragma unroll
    for (int i = 0; i < 8; ++i) {
        pr[i] += __shfl_xor_sync(0xffffffffu, pr[i], 1);
        pr[i] += __shfl_xor_sync(0xffffffffu, pr[i], 2);
    }

    if (valid) {
        float o0 = pr[0], o1 = pr[4];
        if (t == 1) { o0 = pr[1]; o1 = pr[5]; }
        if (t == 2) { o0 = pr[2]; o1 = pr[6]; }
        if (t == 3) { o0 = pr[3]; o1 = pr[7]; }
        out[point * 8 + t]     = o0;
        out[point * 8 + 4 + t] = o1;
    }
}

extern "C" void kernel_launch(void* const* d_in, const int* in_sizes, int n_in,
                              void* d_out, int out_size)
{
    const float* positions  = (const float*)d_in[0];
    const float* features   = (const float*)d_in[1];
    const float* kernel     = (const float*)d_in[2];
    const int*   neighbors  = (const int*)d_in[3];
    const int*   row_splits = (const int*)d_in[4];
    float*       out        = (float*)d_out;

    int n_pts   = in_sizes[0] / 2;
    int n_edges = in_sizes[3];

    int blocks = (n_pts + PTS_PER_BLOCK - 1) / PTS_PER_BLOCK;
    rbf_layer_kernel<<<blocks, BLOCK_THREADS>>>(
        (const float2*)positions, features, kernel, neighbors, row_splits,
        out, n_pts, n_edges);
}

// round 16
// speedup vs baseline: 1.0060x; 1.0060x over previous
#include <cuda_runtime.h>
#include <math.h>

// rbfLayer, round 16: R14 shell VERBATIM (proven best, 31.5us: 256-thread
// blocks, block barrier immediately after phase 1, barrier-free mainloop+
// epilogue tail) + the R15-verified domain-specialized hat decode only
// (~20 lat-4 instr, algebraically exact on the input domain).
// Falsified levers kept OUT: software prefetch (R9/R13), decoded-weight smem
// (R11), K-via-LDG (R12), deferred barrier / syncwarp handoff (R15).

#define PTS_PER_BLOCK 64
#define BLOCK_THREADS 256
#define SSW_STRIDE 18          // float2 per point row (16 + 2 pad)

typedef unsigned long long u64;

__device__ __forceinline__ u64 pack2(float lo, float hi) {
    u64 r;
    asm("mov.b64 %0, {%1,%2};" : "=l"(r)
        : "r"(__float_as_int(lo)), "r"(__float_as_int(hi)));
    return r;
}
__device__ __forceinline__ void unpack2(u64 v, float& lo, float& hi) {
    int a, b;
    asm("mov.b64 {%0,%1}, %2;" : "=r"(a), "=r"(b) : "l"(v));
    lo = __int_as_float(a); hi = __int_as_float(b);
}
__device__ __forceinline__ u64 fma2(u64 a, u64 b, u64 c) {
    u64 d;
    asm("fma.rn.f32x2 %0, %1, %2, %3;" : "=l"(d) : "l"(a), "l"(b), "l"(c));
    return d;
}
__device__ __forceinline__ u64 mul2(u64 a, u64 b) {
    u64 d;
    asm("mul.rn.f32x2 %0, %1, %2;" : "=l"(d) : "l"(a), "l"(b));
    return d;
}
__device__ __forceinline__ u64 add2(u64 a, u64 b) {
    u64 d;
    asm("add.rn.f32x2 %0, %1, %2;" : "=l"(d) : "l"(a), "l"(b));
    return d;
}

__device__ __forceinline__ void edge_geom(float dx, float dy,
                                          float& sr, float& sa) {
    float d2 = fmaxf(fmaf(dx, dx, dy * dy), 1e-24f);
    float rinv = rsqrtf(d2);
    sr = d2 * rinv * 1.5f;

    float ax = fabsf(dx), ay = fabsf(dy);
    float mn = fminf(ax, ay);
    float mx = fmaxf(fmaxf(ax, ay), 1e-30f);
    float tq = __fdividef(mn, mx);
    float t2 = tq * tq;
    float pl = -0.0117212f;
    pl = fmaf(pl, t2, 0.05265332f);
    pl = fmaf(pl, t2, -0.11643287f);
    pl = fmaf(pl, t2, 0.19354346f);
    pl = fmaf(pl, t2, -0.33262347f);
    pl = fmaf(pl, t2, 0.99997726f);
    float ang = pl * tq;
    if (ay > ax) ang = 1.5707963267948966f - ang;
    if (dx < 0.0f) ang = 3.141592653589793f - ang;
    float th = ang * 0.3183098861837907f;
    th = (dy < 0.0f) ? -th : th;
    sa = fmaf(th, 2.0f, 2.0f);
}

// Domain-specialized branch-free hat decode (~20 lat-4 fma-pipe instr):
//   sr in [0, 2.14): wr0 = max(0,1-sr); wr3 = max(0, sr-2)  (exact on domain)
//   sa in [0, 4]   : wa0 = max(0, max(1-sa, sa-3))          (cyclic wrap)
__device__ __forceinline__ void decode_w(float sr, float sa,
                                         float4& WA, float4& WR) {
    float s1 = sa - 1.0f;
    float s2 = sa - 2.0f;
    float s3 = sa - 3.0f;
    WA.x = fmaxf(0.0f, fmaxf(1.0f - sa, s3));
    WA.y = fmaxf(0.0f, 1.0f - fabsf(s1));
    WA.z = fmaxf(0.0f, 1.0f - fabsf(s2));
    WA.w = fmaxf(0.0f, 1.0f - fabsf(s3));

    float r1 = sr - 1.0f;
    float r2 = sr - 2.0f;
    WR.x = fmaxf(0.0f, 1.0f - sr);
    WR.y = fmaxf(0.0f, 1.0f - fabsf(r1));
    WR.z = fmaxf(0.0f, 1.0f - fabsf(r2));
    WR.w = fmaxf(0.0f, r2);
}

__device__ __forceinline__ void accum16(const float4& WA, const float4& WR,
                                        u64 fv2, u64 Zp[16]) {
    u64 t0 = mul2(pack2(WA.x, WA.x), fv2);
    u64 t1 = mul2(pack2(WA.y, WA.y), fv2);
    u64 t2 = mul2(pack2(WA.z, WA.z), fv2);
    u64 t3 = mul2(pack2(WA.w, WA.w), fv2);
    u64 r0 = pack2(WR.x, WR.x);
    u64 r1 = pack2(WR.y, WR.y);
    u64 r2 = pack2(WR.z, WR.z);
    u64 r3 = pack2(WR.w, WR.w);

    Zp[0]  = fma2(r0, t0, Zp[0]);   Zp[1]  = fma2(r0, t1, Zp[1]);
    Zp[2]  = fma2(r0, t2, Zp[2]);   Zp[3]  = fma2(r0, t3, Zp[3]);
    Zp[4]  = fma2(r1, t0, Zp[4]);   Zp[5]  = fma2(r1, t1, Zp[5]);
    Zp[6]  = fma2(r1, t2, Zp[6]);   Zp[7]  = fma2(r1, t3, Zp[7]);
    Zp[8]  = fma2(r2, t0, Zp[8]);   Zp[9]  = fma2(r2, t1, Zp[9]);
    Zp[10] = fma2(r2, t2, Zp[10]);  Zp[11] = fma2(r2, t3, Zp[11]);
    Zp[12] = fma2(r3, t0, Zp[12]);  Zp[13] = fma2(r3, t1, Zp[13]);
    Zp[14] = fma2(r3, t2, Zp[14]);  Zp[15] = fma2(r3, t3, Zp[15]);
}

__global__ __launch_bounds__(BLOCK_THREADS, 4)
void rbf_layer_kernel(const float2* __restrict__ pos,
                      const float*  __restrict__ feat,
                      const float*  __restrict__ kern,
                      const int*    __restrict__ nbrs,
                      const int*    __restrict__ rsp,
                      float*        __restrict__ out,
                      int n_pts, int n_edges)
{
    __shared__ ulonglong2 sk2[8 * 8 * 4];               // 4 KB epilogue K
    __shared__ float2 ssw[PTS_PER_BLOCK * SSW_STRIDE];  // 9.2 KB (sr,sa)

    int tid = threadIdx.x;

    // one entry per thread (256 == table size)
    {
        int idx = tid;
        int tt  = idx & 3;
        int nm2 = (idx >> 2) & 7;
        int i   = idx >> 5;
        int n0 = 2 * nm2, n1 = 2 * nm2 + 1;
        ulonglong2 v;
        v.x = pack2(kern[(i * 8 + 2 * tt)     * 16 + n0],
                    kern[(i * 8 + 2 * tt + 1) * 16 + n0]);
        v.y = pack2(kern[(i * 8 + 2 * tt)     * 16 + n1],
                    kern[(i * 8 + 2 * tt + 1) * 16 + n1]);
        sk2[idx] = v;
    }

    int p0 = blockIdx.x * PTS_PER_BLOCK;

    // ---- Phase 1: geometry -> smem (uniform-row assumption; phase 2
    //      verifies beg==16*point && cnt==16 before using it) ----
    {
        int ptl = tid >> 2;                 // local point 0..63
        int g   = tid & 3;                  // edge quad 0..3
        int e0  = (p0 + ptl) * 16 + g * 4;
        int4 nbq;
        if (e0 + 3 < n_edges) {
            nbq = __ldg((const int4*)(nbrs + e0));
        } else {
            nbq.x = (e0 + 0 < n_edges) ? __ldg(nbrs + e0 + 0) : 0;
            nbq.y = (e0 + 1 < n_edges) ? __ldg(nbrs + e0 + 1) : 0;
            nbq.z = (e0 + 2 < n_edges) ? __ldg(nbrs + e0 + 2) : 0;
            nbq.w = (e0 + 3 < n_edges) ? __ldg(nbrs + e0 + 3) : 0;
        }

        int pidx = p0 + ptl;
        float2 pp = __ldg(&pos[(pidx < n_pts) ? pidx : 0]);
        float2 q0 = __ldg(&pos[nbq.x]);
        float2 q1 = __ldg(&pos[nbq.y]);
        float2 q2 = __ldg(&pos[nbq.z]);
        float2 q3 = __ldg(&pos[nbq.w]);

        float4* dst = (float4*)&ssw[ptl * SSW_STRIDE + g * 4];
        float sr0, sa0, sr1, sa1;
        edge_geom(q0.x - pp.x, q0.y - pp.y, sr0, sa0);
        edge_geom(q1.x - pp.x, q1.y - pp.y, sr1, sa1);
        dst[0] = make_float4(sr0, sa0, sr1, sa1);       // STS.128
        edge_geom(q2.x - pp.x, q2.y - pp.y, sr0, sa0);
        edge_geom(q3.x - pp.x, q3.y - pp.y, sr1, sa1);
        dst[1] = make_float4(sr0, sa0, sr1, sa1);       // STS.128
    }
    __syncthreads();

    // ---- Phase 2 ----
    int point = p0 + (tid >> 2);
    int t     = tid & 3;

    bool valid = (point < n_pts);
    int pclamp = valid ? point : 0;

    int beg = valid ? __ldg(rsp + pclamp)     : 0;
    int end = valid ? __ldg(rsp + pclamp + 1) : 0;
    int cnt = end - beg;

    bool fast = valid && (cnt == 16) && (beg == (point << 4));

    const float2* f2 = (const float2*)feat;

    u64 Zp[16];
    #pragma unroll
    for (int k = 0; k < 16; ++k) Zp[k] = 0ull;

    if (fast) {
        int lpt = point - p0;
        const float2* swp = &ssw[lpt * SSW_STRIDE];
        const int4* nb4 = (const int4*)(nbrs + beg);

        #pragma unroll
        for (int g = 0; g < 4; ++g) {
            int4 nbq = __ldg(nb4 + g);      // broadcast, L1-hot from phase 1
            float2 Fa = __ldg(&f2[(unsigned)nbq.x * 4 + t]);
            float2 Fb = __ldg(&f2[(unsigned)nbq.y * 4 + t]);
            float2 Fc = __ldg(&f2[(unsigned)nbq.z * 4 + t]);
            float2 Fd = __ldg(&f2[(unsigned)nbq.w * 4 + t]);

            float4 WA, WR;
            {
                float4 s01 = *(const float4*)(swp + g * 4);
                decode_w(s01.x, s01.y, WA, WR); accum16(WA, WR, pack2(Fa.x, Fa.y), Zp);
                decode_w(s01.z, s01.w, WA, WR); accum16(WA, WR, pack2(Fb.x, Fb.y), Zp);
            }
            {
                float4 s23 = *(const float4*)(swp + g * 4 + 2);
                decode_w(s23.x, s23.y, WA, WR); accum16(WA, WR, pack2(Fc.x, Fc.y), Zp);
                decode_w(s23.z, s23.w, WA, WR); accum16(WA, WR, pack2(Fd.x, Fd.y), Zp);
            }
        }
    } else if (valid) {
        const float2 pp = __ldg(&pos[pclamp]);
        for (int e = beg; e < end; ++e) {
            int nb = __ldg(nbrs + e);
            float2 q = __ldg(&pos[nb]);
            float sr, sa;
            edge_geom(q.x - pp.x, q.y - pp.y, sr, sa);
            float4 WA, WR;
            decode_w(sr, sa, WA, WR);
            float2 fv = __ldg(&f2[nb * 4 + t]);
            accum16(WA, WR, pack2(fv.x, fv.y), Zp);
        }
    }

    // ---- Epilogue: smem K, two dependency chains per output ----
    float pr[8];
    #pragma unroll
    for (int i = 0; i < 8; ++i) {
        u64 a0 = 0ull, a1 = 0ull;
        #pragma unroll
        for (int nm2 = 0; nm2 < 8; nm2 += 2) {
            ulonglong2 k0 = sk2[(i * 8 + nm2)     * 4 + t];
            ulonglong2 k1 = sk2[(i * 8 + nm2 + 1) * 4 + t];
            a0 = fma2(k0.x, Zp[2 * nm2],     a0);
            a0 = fma2(k0.y, Zp[2 * nm2 + 1], a0);
            a1 = fma2(k1.x, Zp[2 * nm2 + 2], a1);
            a1 = fma2(k1.y, Zp[2 * nm2 + 3], a1);
        }
        u64 acc = add2(a0, a1);
        float lo, hi;
        unpack2(acc, lo, hi);
        pr[i] = lo + hi;
    }

    #pragma unroll
    for (int i = 0; i < 8; ++i) {
        pr[i] += __shfl_xor_sync(0xffffffffu, pr[i], 1);
        pr[i] += __shfl_xor_sync(0xffffffffu, pr[i], 2);
    }

    if (valid) {
        float o0 = pr[0], o1 = pr[4];
        if (t == 1) { o0 = pr[1]; o1 = pr[5]; }
        if (t == 2) { o0 = pr[2]; o1 = pr[6]; }
        if (t == 3) { o0 = pr[3]; o1 = pr[7]; }
        out[point * 8 + t]     = o0;
        out[point * 8 + 4 + t] = o1;
    }
}

extern "C" void kernel_launch(void* const* d_in, const int* in_sizes, int n_in,
                              void* d_out, int out_size)
{
    const float* positions  = (const float*)d_in[0];
    const float* features   = (const float*)d_in[1];
    const float* kernel     = (const float*)d_in[2];
    const int*   neighbors  = (const int*)d_in[3];
    const int*   row_splits = (const int*)d_in[4];
    float*       out        = (float*)d_out;

    int n_pts   = in_sizes[0] / 2;
    int n_edges = in_sizes[3];

    int blocks = (n_pts + PTS_PER_BLOCK - 1) / PTS_PER_BLOCK;
    rbf_layer_kernel<<<blocks, BLOCK_THREADS>>>(
        (const float2*)positions, features, kernel, neighbors, row_splits,
        out, n_pts, n_edges);
}

// round 17
// speedup vs baseline: 1.1941x; 1.1870x over previous
#include <cuda_runtime.h>
#include <math.h>

// rbfLayer, round 17: R14 restored BYTE-EXACT (best measured: 31.5us).
// R15 (decode trim + barrier move) and R16 (decode trim only) both regressed
// to ~37.4us -> the trimmed decode is the falsified lever (its "redundant"
// ops lived in the gather/LDS latency shadow and kept warps issue-eligible).
// This round is a controlled single-variable revert + reproducibility check.
// Falsified levers OUT: software prefetch (R9/R13), decoded-weight smem (R11),
// K-via-LDG (R12), deferred barrier (R15), trimmed decode (R15/R16).

#define PTS_PER_BLOCK 64
#define BLOCK_THREADS 256
#define SSW_STRIDE 18          // float2 per point row (16 + 2 pad)

typedef unsigned long long u64;

__device__ __forceinline__ u64 pack2(float lo, float hi) {
    u64 r;
    asm("mov.b64 %0, {%1,%2};" : "=l"(r)
        : "r"(__float_as_int(lo)), "r"(__float_as_int(hi)));
    return r;
}
__device__ __forceinline__ void unpack2(u64 v, float& lo, float& hi) {
    int a, b;
    asm("mov.b64 {%0,%1}, %2;" : "=r"(a), "=r"(b) : "l"(v));
    lo = __int_as_float(a); hi = __int_as_float(b);
}
__device__ __forceinline__ u64 fma2(u64 a, u64 b, u64 c) {
    u64 d;
    asm("fma.rn.f32x2 %0, %1, %2, %3;" : "=l"(d) : "l"(a), "l"(b), "l"(c));
    return d;
}
__device__ __forceinline__ u64 mul2(u64 a, u64 b) {
    u64 d;
    asm("mul.rn.f32x2 %0, %1, %2;" : "=l"(d) : "l"(a), "l"(b));
    return d;
}
__device__ __forceinline__ u64 add2(u64 a, u64 b) {
    u64 d;
    asm("add.rn.f32x2 %0, %1, %2;" : "=l"(d) : "l"(a), "l"(b));
    return d;
}

__device__ __forceinline__ void edge_geom(float dx, float dy,
                                          float& sr, float& sa) {
    float d2 = fmaxf(fmaf(dx, dx, dy * dy), 1e-24f);
    float rinv = rsqrtf(d2);
    sr = d2 * rinv * 1.5f;

    float ax = fabsf(dx), ay = fabsf(dy);
    float mn = fminf(ax, ay);
    float mx = fmaxf(fmaxf(ax, ay), 1e-30f);
    float tq = __fdividef(mn, mx);
    float t2 = tq * tq;
    float pl = -0.0117212f;
    pl = fmaf(pl, t2, 0.05265332f);
    pl = fmaf(pl, t2, -0.11643287f);
    pl = fmaf(pl, t2, 0.19354346f);
    pl = fmaf(pl, t2, -0.33262347f);
    pl = fmaf(pl, t2, 0.99997726f);
    float ang = pl * tq;
    if (ay > ax) ang = 1.5707963267948966f - ang;
    if (dx < 0.0f) ang = 3.141592653589793f - ang;
    float th = ang * 0.3183098861837907f;
    th = (dy < 0.0f) ? -th : th;
    sa = fmaf(th, 2.0f, 2.0f);
}

// Branch-free PoU hat decode: only FADD/FABS/FMNMX, all lat-4.
// (R14 form — the extra wrap terms double as latency-shadow filler.)
__device__ __forceinline__ void decode_w(float sr, float sa,
                                         float4& WA, float4& WR) {
    float a0 = fabsf(sa);
    float a1 = fabsf(sa - 1.0f);
    float a2 = fabsf(sa - 2.0f);
    float a3 = fabsf(sa - 3.0f);
    WA.x = fmaxf(0.0f, fmaxf(1.0f - a0, a0 - 3.0f));
    WA.y = fmaxf(0.0f, fmaxf(1.0f - a1, a1 - 3.0f));
    WA.z = fmaxf(0.0f, fmaxf(1.0f - a2, a2 - 3.0f));
    WA.w = fmaxf(0.0f, fmaxf(1.0f - a3, a3 - 3.0f));

    WR.x = fmaxf(0.0f, 1.0f - fabsf(sr));
    WR.y = fmaxf(0.0f, 1.0f - fabsf(sr - 1.0f));
    WR.z = fmaxf(0.0f, 1.0f - fabsf(sr - 2.0f));
    WR.w = fmaxf(0.0f, 1.0f - fabsf(sr - 3.0f));
}

__device__ __forceinline__ void accum16(const float4& WA, const float4& WR,
                                        u64 fv2, u64 Zp[16]) {
    u64 t0 = mul2(pack2(WA.x, WA.x), fv2);
    u64 t1 = mul2(pack2(WA.y, WA.y), fv2);
    u64 t2 = mul2(pack2(WA.z, WA.z), fv2);
    u64 t3 = mul2(pack2(WA.w, WA.w), fv2);
    u64 r0 = pack2(WR.x, WR.x);
    u64 r1 = pack2(WR.y, WR.y);
    u64 r2 = pack2(WR.z, WR.z);
    u64 r3 = pack2(WR.w, WR.w);

    Zp[0]  = fma2(r0, t0, Zp[0]);   Zp[1]  = fma2(r0, t1, Zp[1]);
    Zp[2]  = fma2(r0, t2, Zp[2]);   Zp[3]  = fma2(r0, t3, Zp[3]);
    Zp[4]  = fma2(r1, t0, Zp[4]);   Zp[5]  = fma2(r1, t1, Zp[5]);
    Zp[6]  = fma2(r1, t2, Zp[6]);   Zp[7]  = fma2(r1, t3, Zp[7]);
    Zp[8]  = fma2(r2, t0, Zp[8]);   Zp[9]  = fma2(r2, t1, Zp[9]);
    Zp[10] = fma2(r2, t2, Zp[10]);  Zp[11] = fma2(r2, t3, Zp[11]);
    Zp[12] = fma2(r3, t0, Zp[12]);  Zp[13] = fma2(r3, t1, Zp[13]);
    Zp[14] = fma2(r3, t2, Zp[14]);  Zp[15] = fma2(r3, t3, Zp[15]);
}

__global__ __launch_bounds__(BLOCK_THREADS, 4)
void rbf_layer_kernel(const float2* __restrict__ pos,
                      const float*  __restrict__ feat,
                      const float*  __restrict__ kern,
                      const int*    __restrict__ nbrs,
                      const int*    __restrict__ rsp,
                      float*        __restrict__ out,
                      int n_pts, int n_edges)
{
    __shared__ ulonglong2 sk2[8 * 8 * 4];               // 4 KB epilogue K
    __shared__ float2 ssw[PTS_PER_BLOCK * SSW_STRIDE];  // 9.2 KB (sr,sa)

    int tid = threadIdx.x;

    // one entry per thread (256 == table size)
    {
        int idx = tid;
        int tt  = idx & 3;
        int nm2 = (idx >> 2) & 7;
        int i   = idx >> 5;
        int n0 = 2 * nm2, n1 = 2 * nm2 + 1;
        ulonglong2 v;
        v.x = pack2(kern[(i * 8 + 2 * tt)     * 16 + n0],
                    kern[(i * 8 + 2 * tt + 1) * 16 + n0]);
        v.y = pack2(kern[(i * 8 + 2 * tt)     * 16 + n1],
                    kern[(i * 8 + 2 * tt + 1) * 16 + n1]);
        sk2[idx] = v;
    }

    int p0 = blockIdx.x * PTS_PER_BLOCK;

    // ---- Phase 1: geometry -> smem (uniform-row assumption; phase 2
    //      verifies beg==16*point && cnt==16 before using it) ----
    {
        int ptl = tid >> 2;                 // local point 0..63
        int g   = tid & 3;                  // edge quad 0..3
        int e0  = (p0 + ptl) * 16 + g * 4;
        int4 nbq;
        if (e0 + 3 < n_edges) {
            nbq = __ldg((const int4*)(nbrs + e0));
        } else {
            nbq.x = (e0 + 0 < n_edges) ? __ldg(nbrs + e0 + 0) : 0;
            nbq.y = (e0 + 1 < n_edges) ? __ldg(nbrs + e0 + 1) : 0;
            nbq.z = (e0 + 2 < n_edges) ? __ldg(nbrs + e0 + 2) : 0;
            nbq.w = (e0 + 3 < n_edges) ? __ldg(nbrs + e0 + 3) : 0;
        }

        int pidx = p0 + ptl;
        float2 pp = __ldg(&pos[(pidx < n_pts) ? pidx : 0]);
        float2 q0 = __ldg(&pos[nbq.x]);
        float2 q1 = __ldg(&pos[nbq.y]);
        float2 q2 = __ldg(&pos[nbq.z]);
        float2 q3 = __ldg(&pos[nbq.w]);

        float4* dst = (float4*)&ssw[ptl * SSW_STRIDE + g * 4];
        float sr0, sa0, sr1, sa1;
        edge_geom(q0.x - pp.x, q0.y - pp.y, sr0, sa0);
        edge_geom(q1.x - pp.x, q1.y - pp.y, sr1, sa1);
        dst[0] = make_float4(sr0, sa0, sr1, sa1);       // STS.128
        edge_geom(q2.x - pp.x, q2.y - pp.y, sr0, sa0);
        edge_geom(q3.x - pp.x, q3.y - pp.y, sr1, sa1);
        dst[1] = make_float4(sr0, sa0, sr1, sa1);       // STS.128
    }
    __syncthreads();

    // ---- Phase 2 ----
    int point = p0 + (tid >> 2);
    int t     = tid & 3;

    bool valid = (point < n_pts);
    int pclamp = valid ? point : 0;

    int beg = valid ? __ldg(rsp + pclamp)     : 0;
    int end = valid ? __ldg(rsp + pclamp + 1) : 0;
    int cnt = end - beg;

    bool fast = valid && (cnt == 16) && (beg == (point << 4));

    const float2* f2 = (const float2*)feat;

    u64 Zp[16];
    #pragma unroll
    for (int k = 0; k < 16; ++k) Zp[k] = 0ull;

    if (fast) {
        int lpt = point - p0;
        const float2* swp = &ssw[lpt * SSW_STRIDE];
        const int4* nb4 = (const int4*)(nbrs + beg);

        #pragma unroll
        for (int g = 0; g < 4; ++g) {
            int4 nbq = __ldg(nb4 + g);      // broadcast, L1-hot from phase 1
            float2 Fa = __ldg(&f2[(unsigned)nbq.x * 4 + t]);
            float2 Fb = __ldg(&f2[(unsigned)nbq.y * 4 + t]);
            float2 Fc = __ldg(&f2[(unsigned)nbq.z * 4 + t]);
            float2 Fd = __ldg(&f2[(unsigned)nbq.w * 4 + t]);

            float4 WA, WR;
            {
                float4 s01 = *(const float4*)(swp + g * 4);
                decode_w(s01.x, s01.y, WA, WR); accum16(WA, WR, pack2(Fa.x, Fa.y), Zp);
                decode_w(s01.z, s01.w, WA, WR); accum16(WA, WR, pack2(Fb.x, Fb.y), Zp);
            }
            {
                float4 s23 = *(const float4*)(swp + g * 4 + 2);
                decode_w(s23.x, s23.y, WA, WR); accum16(WA, WR, pack2(Fc.x, Fc.y), Zp);
                decode_w(s23.z, s23.w, WA, WR); accum16(WA, WR, pack2(Fd.x, Fd.y), Zp);
            }
        }
    } else if (valid) {
        const float2 pp = __ldg(&pos[pclamp]);
        for (int e = beg; e < end; ++e) {
            int nb = __ldg(nbrs + e);
            float2 q = __ldg(&pos[nb]);
            float sr, sa;
            edge_geom(q.x - pp.x, q.y - pp.y, sr, sa);
            float4 WA, WR;
            decode_w(sr, sa, WA, WR);
            float2 fv = __ldg(&f2[nb * 4 + t]);
            accum16(WA, WR, pack2(fv.x, fv.y), Zp);
        }
    }

    // ---- Epilogue: smem K, two dependency chains per output ----
    float pr[8];
    #pragma unroll
    for (int i = 0; i < 8; ++i) {
        u64 a0 = 0ull, a1 = 0ull;
        #pragma unroll
        for (int nm2 = 0; nm2 < 8; nm2 += 2) {
            ulonglong2 k0 = sk2[(i * 8 + nm2)     * 4 + t];
            ulonglong2 k1 = sk2[(i * 8 + nm2 + 1) * 4 + t];
            a0 = fma2(k0.x, Zp[2 * nm2],     a0);
            a0 = fma2(k0.y, Zp[2 * nm2 + 1], a0);
            a1 = fma2(k1.x, Zp[2 * nm2 + 2], a1);
            a1 = fma2(k1.y, Zp[2 * nm2 + 3], a1);
        }
        u64 acc = add2(a0, a1);
        float lo, hi;
        unpack2(acc, lo, hi);
        pr[i] = lo + hi;
    }

    #pragma unroll
    for (int i = 0; i < 8; ++i) {
        pr[i] += __shfl_xor_sync(0xffffffffu, pr[i], 1);
        pr[i] += __shfl_xor_sync(0xffffffffu, pr[i], 2);
    }

    if (valid) {
        float o0 = pr[0], o1 = pr[4];
        if (t == 1) { o0 = pr[1]; o1 = pr[5]; }
        if (t == 2) { o0 = pr[2]; o1 = pr[6]; }
        if (t == 3) { o0 = pr[3]; o1 = pr[7]; }
        out[point * 8 + t]     = o0;
        out[point * 8 + 4 + t] = o1;
    }
}

extern "C" void kernel_launch(void* const* d_in, const int* in_sizes, int n_in,
                              void* d_out, int out_size)
{
    const float* positions  = (const float*)d_in[0];
    const float* features   = (const float*)d_in[1];
    const float* kernel     = (const float*)d_in[2];
    const int*   neighbors  = (const int*)d_in[3];
    const int*   row_splits = (const int*)d_in[4];
    float*       out        = (float*)d_out;

    int n_pts   = in_sizes[0] / 2;
    int n_edges = in_sizes[3];

    int blocks = (n_pts + PTS_PER_BLOCK - 1) / PTS_PER_BLOCK;
    rbf_layer_kernel<<<blocks, BLOCK_THREADS>>>(
        (const float2*)positions, features, kernel, neighbors, row_splits,
        out, n_pts, n_edges);
}